// round 16
// baseline (speedup 1.0000x reference)
#include <cuda_runtime.h>
#include <math.h>
#include <stdint.h>

#define HIDDEN 4096
#define SEQ 2048
#define NHEADS 32
#define NKV 8
#define HD 128

extern "C" __device__ float __nv_expf(float);   // libdevice exp == XLA's lowering

// ---------------- device scratch (static, no runtime allocation) ----------------
__device__ int8_t g_X8q[16777216];
__device__ int8_t g_X8k[16777216];
__device__ int8_t g_X8v[16777216];
__device__ int8_t g_W8q[16777216];
__device__ int8_t g_W8k[4194304];
__device__ int8_t g_W8v[4194304];
__device__ int8_t g_W8o[16777216];
__device__ float  g_Xsq[12288], g_Xsk[12288], g_Xsv[12288], g_Xso[12288];
__device__ float  g_Wsq[12288], g_Wsk[3072],  g_Wsv[3072],  g_Wso[12288];
__device__ float  g_Qp[16777216];  // Q projection (4096 x 4096)
__device__ float  g_Kp[4194304];   // K projection (4096 x 1024)
__device__ float  g_Vp[4194304];   // V projection (4096 x 1024)
__device__ float  g_AO[16777216];  // attention output (4096 x 4096)
__device__ float  g_S[268435456];  // scores spill buffer [64][2048][2048]

// ---------------- int8 m16n8k32 tensor-core mma, s32 accumulate (EXACT) ----------------
__device__ __forceinline__ void mma_s8(int d[4],
    unsigned a0, unsigned a1, unsigned a2, unsigned a3,
    unsigned b0, unsigned b1)
{
    asm("mma.sync.aligned.m16n8k32.row.col.s32.s8.s8.s32 "
        "{%0,%1,%2,%3},{%4,%5,%6,%7},{%8,%9},{%0,%1,%2,%3};"
        : "+r"(d[0]), "+r"(d[1]), "+r"(d[2]), "+r"(d[3])
        : "r"(a0), "r"(a1), "r"(a2), "r"(a3), "r"(b0), "r"(b1));
}

// ---------------- cp.async helpers ----------------
__device__ __forceinline__ void cp16(void* smem, const void* g) {
    unsigned s = (unsigned)__cvta_generic_to_shared(smem);
    asm volatile("cp.async.cg.shared.global [%0], [%1], 16;" :: "r"(s), "l"(g));
}
#define CP_COMMIT() asm volatile("cp.async.commit_group;")

// ---------------- quant core (VALIDATED recip-mul semantics) ----------------
__device__ __forceinline__ void quant_phase(
    const float* __restrict__ srow, const int* __restrict__ idx,
    int* smax, int row, int t, int base, int g,
    float qmax, float rqmax,
    int8_t* __restrict__ dst8, float* __restrict__ scales)
{
    if (t < 3) smax[t] = 0;
    __syncthreads();

    float vals[16];
    float lm = 0.f;
    #pragma unroll
    for (int i = 0; i < 16; i++) {
        vals[i] = srow[idx[base + i]];
        lm = fmaxf(lm, fabsf(vals[i]));
    }
    atomicMax(&smax[g], __float_as_int(lm));   // nonneg floats order as ints
    __syncthreads();

    const float maxv = __int_as_float(smax[g]);
    const float sc   = __fadd_rn(__fmul_rn(maxv, rqmax), 1e-8f);
    const float rsc  = __fdiv_rn(1.0f, sc);
    if (t == 0 || t == 208 || t == 240)
        scales[row * 3 + g] = sc;

    int b[16];
    #pragma unroll
    for (int i = 0; i < 16; i++) {
        float q = rintf(__fmul_rn(vals[i], rsc));   // round(a * (1/s)), half-even
        q = fminf(fmaxf(q, -qmax), qmax);
        b[i] = (int)q;
    }
    int4 pk;
    pk.x = (b[0] & 255) | ((b[1] & 255) << 8) | ((b[2] & 255) << 16) | ((b[3] & 255) << 24);
    pk.y = (b[4] & 255) | ((b[5] & 255) << 8) | ((b[6] & 255) << 16) | ((b[7] & 255) << 24);
    pk.z = (b[8] & 255) | ((b[9] & 255) << 8) | ((b[10] & 255) << 16) | ((b[11] & 255) << 24);
    pk.w = (b[12] & 255) | ((b[13] & 255) << 8) | ((b[14] & 255) << 16) | ((b[15] & 255) << 24);
    *(int4*)&dst8[(size_t)row * 4096 + base] = pk;
    __syncthreads();   // phase complete before smax reuse
}

// single-permutation quant (weights, AO)
__global__ void __launch_bounds__(256) quant8_rows_kernel(
    const float* __restrict__ src, const int* __restrict__ idx,
    int8_t* __restrict__ dst8, float* __restrict__ scales)
{
    __shared__ float srow[4096];
    __shared__ int smax[3];
    const int row = blockIdx.x;
    const int t = threadIdx.x;
    const float* s = src + (size_t)row * 4096;
    #pragma unroll
    for (int l = 0; l < 4; l++) {
        int f = t + l * 256;
        *(float4*)&srow[f * 4] = *(const float4*)&s[f * 4];
    }
    __syncthreads();
    const int base = t * 16;
    const int g = (base < 3328) ? 0 : (base < 3840 ? 1 : 2);
    const float qmax  = (g == 0) ? 7.f : (g == 1 ? 31.f : 127.f);
    const float rqmax = (g == 0) ? (1.0f / 7.0f) : (g == 1 ? (1.0f / 31.0f) : (1.0f / 127.0f));
    quant_phase(srow, idx, smax, row, t, base, g, qmax, rqmax, dst8, scales);
}

// fused 3-permutation quant (hidden states -> X8q, X8k, X8v; hidden read once)
__global__ void __launch_bounds__(256) quant8x3_kernel(
    const float* __restrict__ src,
    const int* __restrict__ i0, const int* __restrict__ i1, const int* __restrict__ i2,
    int8_t* __restrict__ d0, int8_t* __restrict__ d1, int8_t* __restrict__ d2,
    float* __restrict__ s0, float* __restrict__ s1, float* __restrict__ s2)
{
    __shared__ float srow[4096];
    __shared__ int smax[3];
    const int row = blockIdx.x;
    const int t = threadIdx.x;
    const float* s = src + (size_t)row * 4096;
    #pragma unroll
    for (int l = 0; l < 4; l++) {
        int f = t + l * 256;
        *(float4*)&srow[f * 4] = *(const float4*)&s[f * 4];
    }
    __syncthreads();
    const int base = t * 16;
    const int g = (base < 3328) ? 0 : (base < 3840 ? 1 : 2);
    const float qmax  = (g == 0) ? 7.f : (g == 1 ? 31.f : 127.f);
    const float rqmax = (g == 0) ? (1.0f / 7.0f) : (g == 1 ? (1.0f / 31.0f) : (1.0f / 127.0f));
    quant_phase(srow, i0, smax, row, t, base, g, qmax, rqmax, d0, s0);
    quant_phase(srow, i1, smax, row, t, base, g, qmax, rqmax, d1, s1);
    quant_phase(srow, i2, smax, row, t, base, g, qmax, rqmax, d2, s2);
}

// ---------------- projection GEMM: EXACT int8 TC, 3-stage cp.async, 1 sync/iter ----------------
#define PROJ_DSMEM (3 * 20480)
__global__ void __launch_bounds__(256) proj_imma_kernel(
    const int8_t* __restrict__ A8, const float* __restrict__ Asc,
    const int8_t* __restrict__ B8, const float* __restrict__ Bsc,
    float* __restrict__ C, int N)
{
    extern __shared__ int8_t smp[];
    __shared__ float sxa[128 * 3];
    __shared__ float sxb[128 * 3];

    const int m0 = blockIdx.y * 128;
    const int n0 = blockIdx.x * 128;
    const int t = threadIdx.x;
    const int w = t >> 5;
    const int lane = t & 31;
    const int gid = lane >> 2;
    const int tg = lane & 3;
    const int wm = w & 3;
    const int wn = w >> 2;

    if (t < 128) {
        #pragma unroll
        for (int g = 0; g < 3; g++) {
            sxa[t * 3 + g] = Asc[(m0 + t) * 3 + g];
            sxb[t * 3 + g] = Bsc[(n0 + t) * 3 + g];
        }
    }

    int acc[2][8][4];
    float tot[2][8][4];
    #pragma unroll
    for (int mf = 0; mf < 2; mf++)
        #pragma unroll
        for (int nf = 0; nf < 8; nf++)
            #pragma unroll
            for (int e = 0; e < 4; e++) { acc[mf][nf][e] = 0; tot[mf][nf][e] = 0.f; }

    const int r = t >> 2;
    const int c16 = (t & 3) * 16;

    // prologue: stages 0, 1
    #pragma unroll
    for (int st = 0; st < 2; st++) {
        int8_t* bA = smp + st * 20480;
        int8_t* bB = bA + 10240;
        #pragma unroll
        for (int l = 0; l < 2; l++) {
            int rr = r + l * 64;
            cp16(&bA[rr * 80 + c16], &A8[(size_t)(m0 + rr) * 4096 + st * 64 + c16]);
            cp16(&bB[rr * 80 + c16], &B8[(size_t)(n0 + rr) * 4096 + st * 64 + c16]);
        }
        CP_COMMIT();
    }

    int gi = 0;
    for (int kt = 0; kt < 64; kt++) {
        if (kt + 2 < 64) asm volatile("cp.async.wait_group 1;");
        else             asm volatile("cp.async.wait_group 0;");
        __syncthreads();            // stage kt visible; slot (kt+2)%3 free for rewrite

        if (kt + 2 < 64) {
            const int st = (kt + 2) % 3;
            const int kk0 = (kt + 2) * 64;
            int8_t* bA = smp + st * 20480;
            int8_t* bB = bA + 10240;
            #pragma unroll
            for (int l = 0; l < 2; l++) {
                int rr = r + l * 64;
                cp16(&bA[rr * 80 + c16], &A8[(size_t)(m0 + rr) * 4096 + kk0 + c16]);
                cp16(&bB[rr * 80 + c16], &B8[(size_t)(n0 + rr) * 4096 + kk0 + c16]);
            }
            CP_COMMIT();
        }

        const int8_t* cA = smp + (kt % 3) * 20480;
        const int8_t* cB = cA + 10240;
        #pragma unroll
        for (int ks = 0; ks < 2; ks++) {
            const int kc = ks * 32;
            unsigned a[2][4];
            #pragma unroll
            for (int mf = 0; mf < 2; mf++) {
                int rr = wm * 32 + mf * 16 + gid;
                a[mf][0] = *(const unsigned*)&cA[rr * 80 + kc + tg * 4];
                a[mf][1] = *(const unsigned*)&cA[(rr + 8) * 80 + kc + tg * 4];
                a[mf][2] = *(const unsigned*)&cA[rr * 80 + kc + 16 + tg * 4];
                a[mf][3] = *(const unsigned*)&cA[(rr + 8) * 80 + kc + 16 + tg * 4];
            }
            #pragma unroll
            for (int nf = 0; nf < 8; nf++) {
                int n = wn * 64 + nf * 8 + gid;
                unsigned b0 = *(const unsigned*)&cB[n * 80 + kc + tg * 4];
                unsigned b1 = *(const unsigned*)&cB[n * 80 + kc + 16 + tg * 4];
                mma_s8(acc[0][nf], a[0][0], a[0][1], a[0][2], a[0][3], b0, b1);
                mma_s8(acc[1][nf], a[1][0], a[1][1], a[1][2], a[1][3], b0, b1);
            }
        }

        const int knext = (kt + 1) * 64;       // group boundaries 3328/3840/4096
        if (knext == 3328 || knext == 3840 || knext == 4096) {
            #pragma unroll
            for (int mf = 0; mf < 2; mf++) {
                int rrel0 = wm * 32 + mf * 16 + gid;
                #pragma unroll
                for (int nf = 0; nf < 8; nf++) {
                    #pragma unroll
                    for (int e = 0; e < 4; e++) {
                        int rrel = rrel0 + (e >> 1) * 8;
                        int crel = wn * 64 + nf * 8 + 2 * tg + (e & 1);
                        float sp = __fmul_rn(sxa[rrel * 3 + gi], sxb[crel * 3 + gi]);
                        float dg = __fmul_rn(sp, __int2float_rn(acc[mf][nf][e]));
                        tot[mf][nf][e] = __fadd_rn(tot[mf][nf][e], dg);   // ((d1+d2)+d3)
                        acc[mf][nf][e] = 0;
                    }
                }
            }
            gi++;
        }
    }

    #pragma unroll
    for (int mf = 0; mf < 2; mf++)
        #pragma unroll
        for (int nf = 0; nf < 8; nf++)
            #pragma unroll
            for (int e = 0; e < 4; e++) {
                int row = m0 + wm * 32 + mf * 16 + gid + (e >> 1) * 8;
                int col = n0 + wn * 64 + nf * 8 + 2 * tg + (e & 1);
                C[(size_t)row * N + col] = tot[mf][nf][e];
            }
}

// ---------------- RoPE (in place), exact IEEE mul/add (VALIDATED) ----------------
__global__ void __launch_bounds__(256) rope_kernel(
    float* __restrict__ x, const float* __restrict__ cs,
    const float* __restrict__ sn, int nheads)
{
    int idx = blockIdx.x * 256 + threadIdx.x;
    int d = idx & 63;
    int h = (idx >> 6) % nheads;
    int token = idx / (nheads * 64);
    float* row = x + ((size_t)token * nheads + h) * HD;
    const float* cr = cs + (size_t)token * HD;
    const float* sr = sn + (size_t)token * HD;
    float a = row[d], b = row[d + 64];
    row[d]      = __fadd_rn(__fmul_rn(a, cr[d]),      __fmul_rn(-b, sr[d]));
    row[d + 64] = __fadd_rn(__fmul_rn(b, cr[d + 64]), __fmul_rn(a, sr[d + 64]));
}

// ---------------- two-pass flash attention with scores spill (bit-identical; LPT order) ----------------
#define FLASH_SMEM ((2 * 64 * 132 + 64 * 68) * 4)
__global__ void __launch_bounds__(256, 2) flash2p_kernel(
    const float* __restrict__ Q, const float* __restrict__ K,
    const float* __restrict__ V, float* __restrict__ O, float* __restrict__ Sbuf)
{
    extern __shared__ float sm[];
    float* Qs = sm;                // [64][132]
    float* Bf = sm + 64 * 132;     // K tile or V tile [64][132]
    float* Ps = sm + 2 * 64 * 132; // [64][68]

    const int qt = 31 - blockIdx.x;            // LPT: heavy blocks first
    const int bh = blockIdx.y;
    const int b = bh >> 5;
    const int h = bh & 31;
    const int kvh = h >> 2;
    const int q0 = qt * 64;
    const int t = threadIdx.x;
    const int tx = t & 15;
    const int ty = t >> 4;
    const float scale = 0.08838834764831845f;   // 128^-0.5
    const float FMIN = -3.40282347e38f;         // finfo(f32).min

    float* Sz = Sbuf + (size_t)bh * SEQ * SEQ;

    const float* Qb = Q + ((size_t)(b * SEQ + q0) * NHEADS + h) * HD;
    #pragma unroll
    for (int l = 0; l < 8; l++) {
        int f = t + l * 256;
        int r = f >> 5;
        int dq = f & 31;
        *(float4*)&Qs[r * 132 + dq * 4] = *(const float4*)&Qb[(size_t)r * 4096 + dq * 4];
    }

    float m_i[4], l_i[4];
    #pragma unroll
    for (int i = 0; i < 4; i++) { m_i[i] = -INFINITY; l_i[i] = 0.f; }

    const int ntiles = qt + 1;

    // ======== PASS A: compute s once (spill), exact row max M and denominator Z ========
    for (int jt = 0; jt < ntiles; jt++) {
        const int k0 = jt * 64;
        const float* Kb = K + ((size_t)(b * SEQ + k0) * NKV + kvh) * HD;
        __syncthreads();
        #pragma unroll
        for (int l = 0; l < 8; l++) {
            int f = t + l * 256;
            int r = f >> 5;
            int dq = f & 31;
            *(float4*)&Bf[r * 132 + dq * 4] = *(const float4*)&Kb[(size_t)r * 1024 + dq * 4];
        }
        __syncthreads();

        float acc[4][4];
        #pragma unroll
        for (int i = 0; i < 4; i++)
            #pragma unroll
            for (int j = 0; j < 4; j++) acc[i][j] = 0.f;
        #pragma unroll 8
        for (int d4 = 0; d4 < 32; d4++) {
            float4 qa[4], kb[4];
            #pragma unroll
            for (int i = 0; i < 4; i++)
                qa[i] = *(const float4*)&Qs[(ty + 16 * i) * 132 + d4 * 4];
            #pragma unroll
            for (int j = 0; j < 4; j++)
                kb[j] = *(const float4*)&Bf[(tx + 16 * j) * 132 + d4 * 4];
            #pragma unroll
            for (int i = 0; i < 4; i++)
                #pragma unroll
                for (int j = 0; j < 4; j++) {
                    acc[i][j] = __fmaf_rn(qa[i].x, kb[j].x, acc[i][j]);
                    acc[i][j] = __fmaf_rn(qa[i].y, kb[j].y, acc[i][j]);
                    acc[i][j] = __fmaf_rn(qa[i].z, kb[j].z, acc[i][j]);
                    acc[i][j] = __fmaf_rn(qa[i].w, kb[j].w, acc[i][j]);
                }
        }

        const bool diag = (jt == qt);
        #pragma unroll
        for (int i = 0; i < 4; i++) {
            int r = ty + 16 * i;
            #pragma unroll
            for (int j = 0; j < 4; j++) {
                int c = tx + 16 * j;
                float s = __fmul_rn(acc[i][j], scale);
                if (diag && c > r) s = FMIN;
                acc[i][j] = s;
                Sz[(size_t)(q0 + r) * SEQ + (k0 + c)] = s;   // spill (thread-local round trip)
            }
        }

        #pragma unroll
        for (int i = 0; i < 4; i++) {
            float rm = fmaxf(fmaxf(acc[i][0], acc[i][1]), fmaxf(acc[i][2], acc[i][3]));
            #pragma unroll
            for (int sft = 1; sft < 16; sft <<= 1)
                rm = fmaxf(rm, __shfl_xor_sync(0xffffffffu, rm, sft));
            float mn = fmaxf(m_i[i], rm);
            float al = (m_i[i] == -INFINITY) ? 0.f : __nv_expf(__fadd_rn(m_i[i], -mn));
            m_i[i] = mn;
            float rs = 0.f;
            #pragma unroll
            for (int j = 0; j < 4; j++)
                rs = __fadd_rn(rs, __nv_expf(__fadd_rn(acc[i][j], -mn)));
            #pragma unroll
            for (int sft = 1; sft < 16; sft <<= 1)
                rs = __fadd_rn(rs, __shfl_xor_sync(0xffffffffu, rs, sft));
            l_i[i] = __fadd_rn(__fmul_rn(l_i[i], al), rs);
        }
    }

    float rZ[4];
    #pragma unroll
    for (int i = 0; i < 4; i++) rZ[i] = __fdiv_rn(1.0f, l_i[i]);

    // ======== PASS B: read spilled s; p = exp(s - M) * (1/Z); O = sum p * v ========
    float o[4][8];
    #pragma unroll
    for (int i = 0; i < 4; i++)
        #pragma unroll
        for (int dd = 0; dd < 8; dd++) o[i][dd] = 0.f;

    for (int jt = 0; jt < ntiles; jt++) {
        const int k0 = jt * 64;
        __syncthreads();

        #pragma unroll
        for (int i = 0; i < 4; i++) {
            int r = ty + 16 * i;
            #pragma unroll
            for (int j = 0; j < 4; j++) {
                int c = tx + 16 * j;
                float s = Sz[(size_t)(q0 + r) * SEQ + (k0 + c)];   // bit-identical readback
                float e = __nv_expf(__fadd_rn(s, -m_i[i]));        // 0 for masked (FMIN)
                Ps[r * 68 + c] = __fmul_rn(e, rZ[i]);
            }
        }

        const float* Vb = V + ((size_t)(b * SEQ + k0) * NKV + kvh) * HD;
        #pragma unroll
        for (int l = 0; l < 8; l++) {
            int f = t + l * 256;
            int r = f >> 5;
            int dq = f & 31;
            *(float4*)&Bf[r * 132 + dq * 4] = *(const float4*)&Vb[(size_t)r * 1024 + dq * 4];
        }
        __syncthreads();

        #pragma unroll 4
        for (int j = 0; j < 64; j++) {
            float pj[4];
            #pragma unroll
            for (int i = 0; i < 4; i++) pj[i] = Ps[(ty + 16 * i) * 68 + j];
            float4 v0 = *(const float4*)&Bf[j * 132 + tx * 8];
            float4 v1 = *(const float4*)&Bf[j * 132 + tx * 8 + 4];
            #pragma unroll
            for (int i = 0; i < 4; i++) {
                o[i][0] = __fmaf_rn(pj[i], v0.x, o[i][0]);
                o[i][1] = __fmaf_rn(pj[i], v0.y, o[i][1]);
                o[i][2] = __fmaf_rn(pj[i], v0.z, o[i][2]);
                o[i][3] = __fmaf_rn(pj[i], v0.w, o[i][3]);
                o[i][4] = __fmaf_rn(pj[i], v1.x, o[i][4]);
                o[i][5] = __fmaf_rn(pj[i], v1.y, o[i][5]);
                o[i][6] = __fmaf_rn(pj[i], v1.z, o[i][6]);
                o[i][7] = __fmaf_rn(pj[i], v1.w, o[i][7]);
            }
        }
    }

    #pragma unroll
    for (int i = 0; i < 4; i++) {
        int r = ty + 16 * i;
        float* dst = O + ((size_t)(b * SEQ + q0 + r) * HIDDEN) + h * HD + tx * 8;
        *(float4*)dst       = make_float4(o[i][0], o[i][1], o[i][2], o[i][3]);
        *(float4*)(dst + 4) = make_float4(o[i][4], o[i][5], o[i][6], o[i][7]);
    }
}

// ---------------- launch: single stream (allocation-free; streams/events are illegal) ----------------
extern "C" void kernel_launch(void* const* d_in, const int* in_sizes, int n_in,
                              void* d_out, int out_size)
{
    const float* hidden = (const float*)d_in[0];
    const float* cosp   = (const float*)d_in[1];
    const float* sinp   = (const float*)d_in[2];
    const float* Wq     = (const float*)d_in[3];
    const float* Wk     = (const float*)d_in[4];
    const float* Wv     = (const float*)d_in[5];
    const float* Wo     = (const float*)d_in[6];
    const int* idx_q    = (const int*)d_in[7];
    const int* idx_k    = (const int*)d_in[8];
    const int* idx_v    = (const int*)d_in[9];
    const int* idx_o    = (const int*)d_in[10];
    float* out = (float*)d_out;

    int8_t *X8q, *X8k, *X8v, *W8q, *W8k, *W8v, *W8o;
    float *Xsq, *Xsk, *Xsv, *Xso, *Wsq, *Wsk, *Wsv, *Wso;
    float *Qp, *Kp, *Vp, *AO, *S;
    cudaGetSymbolAddress((void**)&X8q, g_X8q);
    cudaGetSymbolAddress((void**)&X8k, g_X8k);
    cudaGetSymbolAddress((void**)&X8v, g_X8v);
    cudaGetSymbolAddress((void**)&W8q, g_W8q);
    cudaGetSymbolAddress((void**)&W8k, g_W8k);
    cudaGetSymbolAddress((void**)&W8v, g_W8v);
    cudaGetSymbolAddress((void**)&W8o, g_W8o);
    cudaGetSymbolAddress((void**)&Xsq, g_Xsq);
    cudaGetSymbolAddress((void**)&Xsk, g_Xsk);
    cudaGetSymbolAddress((void**)&Xsv, g_Xsv);
    cudaGetSymbolAddress((void**)&Xso, g_Xso);
    cudaGetSymbolAddress((void**)&Wsq, g_Wsq);
    cudaGetSymbolAddress((void**)&Wsk, g_Wsk);
    cudaGetSymbolAddress((void**)&Wsv, g_Wsv);
    cudaGetSymbolAddress((void**)&Wso, g_Wso);
    cudaGetSymbolAddress((void**)&Qp, g_Qp);
    cudaGetSymbolAddress((void**)&Kp, g_Kp);
    cudaGetSymbolAddress((void**)&Vp, g_Vp);
    cudaGetSymbolAddress((void**)&AO, g_AO);
    cudaGetSymbolAddress((void**)&S,  g_S);

    cudaFuncSetAttribute(flash2p_kernel, cudaFuncAttributeMaxDynamicSharedMemorySize, FLASH_SMEM);
    cudaFuncSetAttribute(proj_imma_kernel, cudaFuncAttributeMaxDynamicSharedMemorySize, PROJ_DSMEM);

    dim3 gQO(32, 32), gKV(8, 32);

    // fused hidden quant (all three permutations; hidden read once)
    quant8x3_kernel<<<4096, 256>>>(hidden, idx_q, idx_k, idx_v,
                                   X8q, X8k, X8v, Xsq, Xsk, Xsv);
    // weight quants
    quant8_rows_kernel<<<4096, 256>>>(Wq, idx_q, W8q, Wsq);
    quant8_rows_kernel<<<1024, 256>>>(Wk, idx_k, W8k, Wsk);
    quant8_rows_kernel<<<1024, 256>>>(Wv, idx_v, W8v, Wsv);
    quant8_rows_kernel<<<4096, 256>>>(Wo, idx_o, W8o, Wso);
    // projections (EXACT int8 tensor cores, pipelined)
    proj_imma_kernel<<<gQO, 256, PROJ_DSMEM>>>(X8q, Xsq, W8q, Wsq, Qp, 4096);
    proj_imma_kernel<<<gKV, 256, PROJ_DSMEM>>>(X8k, Xsk, W8k, Wsk, Kp, 1024);
    proj_imma_kernel<<<gKV, 256, PROJ_DSMEM>>>(X8v, Xsv, W8v, Wsv, Vp, 1024);
    // RoPE (exact elementwise)
    rope_kernel<<<(4096 * 32 * 64) / 256, 256>>>(Qp, cosp, sinp, 32);
    rope_kernel<<<(4096 * 8 * 64) / 256, 256>>>(Kp, cosp, sinp, 8);
    // attention (two-pass with scores spill; bit-identical numerics)
    flash2p_kernel<<<dim3(32, 64), 256, FLASH_SMEM>>>(Qp, Kp, Vp, AO, S);
    // O projection (reuse X8q for quantized AO)
    quant8_rows_kernel<<<4096, 256>>>(AO, idx_o, X8q, Xso);
    proj_imma_kernel<<<gQO, 256, PROJ_DSMEM>>>(X8q, Xso, W8o, Wso, out, 4096);
}

// round 17
// speedup vs baseline: 1.0348x; 1.0348x over previous
#include <cuda_runtime.h>
#include <math.h>
#include <stdint.h>

#define HIDDEN 4096
#define SEQ 2048
#define NHEADS 32
#define NKV 8
#define HD 128

extern "C" __device__ float __nv_expf(float);   // libdevice exp == XLA's lowering

// ---------------- device scratch (static, no runtime allocation) ----------------
__device__ int8_t g_X8[16777216];  // quantized activations, int8 codes (4096 x 4096)
__device__ int8_t g_W8[16777216];  // quantized weights, int8 codes   (<=4096 x 4096)
__device__ float  g_Xs[12288];     // activation scales [row][3]
__device__ float  g_Ws[12288];     // weight scales     [row][3]
__device__ float  g_Qp[16777216];  // Q projection (4096 x 4096)
__device__ float  g_Kp[4194304];   // K projection (4096 x 1024)
__device__ float  g_Vp[4194304];   // V projection (4096 x 1024)
__device__ float  g_AO[16777216];  // attention output (4096 x 4096)

// ---------------- int8 m16n8k32 tensor-core mma, s32 accumulate (EXACT) ----------------
__device__ __forceinline__ void mma_s8(int d[4],
    unsigned a0, unsigned a1, unsigned a2, unsigned a3,
    unsigned b0, unsigned b1)
{
    asm("mma.sync.aligned.m16n8k32.row.col.s32.s8.s8.s32 "
        "{%0,%1,%2,%3},{%4,%5,%6,%7},{%8,%9},{%0,%1,%2,%3};"
        : "+r"(d[0]), "+r"(d[1]), "+r"(d[2]), "+r"(d[3])
        : "r"(a0), "r"(a1), "r"(a2), "r"(a3), "r"(b0), "r"(b1));
}

// ---------------- cp.async helpers ----------------
__device__ __forceinline__ void cp16(void* smem, const void* g) {
    unsigned s = (unsigned)__cvta_generic_to_shared(smem);
    asm volatile("cp.async.cg.shared.global [%0], [%1], 16;" :: "r"(s), "l"(g));
}
#define CP_COMMIT() asm volatile("cp.async.commit_group;")

// ---------------- fake-quant + gather (VALIDATED recip-mul semantics) -> int8 + scales ----------------
__global__ void __launch_bounds__(256) quant8_rows_kernel(
    const float* __restrict__ src, const int* __restrict__ idx,
    int8_t* __restrict__ dst8, float* __restrict__ scales)
{
    __shared__ float srow[4096];
    __shared__ int smax[3];
    const int row = blockIdx.x;
    const int t = threadIdx.x;
    const float* s = src + (size_t)row * 4096;

    #pragma unroll
    for (int l = 0; l < 4; l++) {
        int f = t + l * 256;
        *(float4*)&srow[f * 4] = *(const float4*)&s[f * 4];
    }
    if (t < 3) smax[t] = 0;
    __syncthreads();

    const int base = t * 16;                  // chunk fully inside one group
    float vals[16];
    float lm = 0.f;
    #pragma unroll
    for (int i = 0; i < 16; i++) {
        vals[i] = srow[idx[base + i]];
        lm = fmaxf(lm, fabsf(vals[i]));
    }
    const int g = (base < 3328) ? 0 : (base < 3840 ? 1 : 2);
    atomicMax(&smax[g], __float_as_int(lm));
    __syncthreads();

    const float qmax  = (g == 0) ? 7.f : (g == 1 ? 31.f : 127.f);
    const float rqmax = (g == 0) ? (1.0f / 7.0f) : (g == 1 ? (1.0f / 31.0f) : (1.0f / 127.0f));
    const float maxv  = __int_as_float(smax[g]);
    const float sc    = __fadd_rn(__fmul_rn(maxv, rqmax), 1e-8f);
    const float rsc   = __fdiv_rn(1.0f, sc);
    if (t == 0 || t == 208 || t == 240)
        scales[row * 3 + g] = sc;

    int8_t* d = dst8 + (size_t)row * 4096;
    #pragma unroll
    for (int i = 0; i < 16; i++) {
        float q = rintf(__fmul_rn(vals[i], rsc));
        q = fminf(fmaxf(q, -qmax), qmax);
        d[base + i] = (int8_t)(int)q;
    }
}

// ---------------- projection GEMM: EXACT int8 TC, 2-stage cp.async pipeline (R14-validated) ----------------
__global__ void __launch_bounds__(256) proj_imma_kernel(
    const int8_t* __restrict__ A8, const float* __restrict__ Asc,
    const int8_t* __restrict__ B8, const float* __restrict__ Bsc,
    float* __restrict__ C, int N)
{
    __shared__ int8_t smA[2][128 * 80];
    __shared__ int8_t smB[2][128 * 80];
    __shared__ float sxa[128 * 3];
    __shared__ float sxb[128 * 3];

    const int m0 = blockIdx.y * 128;
    const int n0 = blockIdx.x * 128;
    const int t = threadIdx.x;
    const int w = t >> 5;
    const int lane = t & 31;
    const int gid = lane >> 2;
    const int tg = lane & 3;
    const int wm = w & 3;
    const int wn = w >> 2;

    if (t < 128) {
        #pragma unroll
        for (int g = 0; g < 3; g++) {
            sxa[t * 3 + g] = Asc[(m0 + t) * 3 + g];
            sxb[t * 3 + g] = Bsc[(n0 + t) * 3 + g];
        }
    }

    int acc[2][8][4];
    float tot[2][8][4];
    #pragma unroll
    for (int mf = 0; mf < 2; mf++)
        #pragma unroll
        for (int nf = 0; nf < 8; nf++)
            #pragma unroll
            for (int e = 0; e < 4; e++) { acc[mf][nf][e] = 0; tot[mf][nf][e] = 0.f; }

    const int r = t >> 2;
    const int c16 = (t & 3) * 16;

    // prologue: stage 0
    {
        #pragma unroll
        for (int l = 0; l < 2; l++) {
            int rr = r + l * 64;
            cp16(&smA[0][rr * 80 + c16], &A8[(size_t)(m0 + rr) * 4096 + 0 + c16]);
            cp16(&smB[0][rr * 80 + c16], &B8[(size_t)(n0 + rr) * 4096 + 0 + c16]);
        }
        CP_COMMIT();
    }

    int gi = 0;
    for (int kt = 0; kt < 64; kt++) {
        const int k0 = kt * 64;
        if (kt + 1 < 64) {
            const int st = (kt + 1) & 1;
            #pragma unroll
            for (int l = 0; l < 2; l++) {
                int rr = r + l * 64;
                cp16(&smA[st][rr * 80 + c16], &A8[(size_t)(m0 + rr) * 4096 + k0 + 64 + c16]);
                cp16(&smB[st][rr * 80 + c16], &B8[(size_t)(n0 + rr) * 4096 + k0 + 64 + c16]);
            }
            CP_COMMIT();
            asm volatile("cp.async.wait_group 1;");
        } else {
            asm volatile("cp.async.wait_group 0;");
        }
        __syncthreads();

        const int8_t* cA = smA[kt & 1];
        const int8_t* cB = smB[kt & 1];
        #pragma unroll
        for (int ks = 0; ks < 2; ks++) {
            const int kc = ks * 32;
            unsigned a[2][4];
            #pragma unroll
            for (int mf = 0; mf < 2; mf++) {
                int rr = wm * 32 + mf * 16 + gid;
                a[mf][0] = *(const unsigned*)&cA[rr * 80 + kc + tg * 4];
                a[mf][1] = *(const unsigned*)&cA[(rr + 8) * 80 + kc + tg * 4];
                a[mf][2] = *(const unsigned*)&cA[rr * 80 + kc + 16 + tg * 4];
                a[mf][3] = *(const unsigned*)&cA[(rr + 8) * 80 + kc + 16 + tg * 4];
            }
            #pragma unroll
            for (int nf = 0; nf < 8; nf++) {
                int n = wn * 64 + nf * 8 + gid;
                unsigned b0 = *(const unsigned*)&cB[n * 80 + kc + tg * 4];
                unsigned b1 = *(const unsigned*)&cB[n * 80 + kc + 16 + tg * 4];
                mma_s8(acc[0][nf], a[0][0], a[0][1], a[0][2], a[0][3], b0, b1);
                mma_s8(acc[1][nf], a[1][0], a[1][1], a[1][2], a[1][3], b0, b1);
            }
        }

        const int knext = k0 + 64;             // group boundaries 3328/3840/4096
        if (knext == 3328 || knext == 3840 || knext == 4096) {
            #pragma unroll
            for (int mf = 0; mf < 2; mf++) {
                int rrel0 = wm * 32 + mf * 16 + gid;
                #pragma unroll
                for (int nf = 0; nf < 8; nf++) {
                    #pragma unroll
                    for (int e = 0; e < 4; e++) {
                        int rrel = rrel0 + (e >> 1) * 8;
                        int crel = wn * 64 + nf * 8 + 2 * tg + (e & 1);
                        float sp = __fmul_rn(sxa[rrel * 3 + gi], sxb[crel * 3 + gi]);
                        float dg = __fmul_rn(sp, __int2float_rn(acc[mf][nf][e]));
                        tot[mf][nf][e] = __fadd_rn(tot[mf][nf][e], dg);   // ((d1+d2)+d3)
                        acc[mf][nf][e] = 0;
                    }
                }
            }
            gi++;
        }
        __syncthreads();
    }

    #pragma unroll
    for (int mf = 0; mf < 2; mf++)
        #pragma unroll
        for (int nf = 0; nf < 8; nf++)
            #pragma unroll
            for (int e = 0; e < 4; e++) {
                int row = m0 + wm * 32 + mf * 16 + gid + (e >> 1) * 8;
                int col = n0 + wn * 64 + nf * 8 + 2 * tg + (e & 1);
                C[(size_t)row * N + col] = tot[mf][nf][e];
            }
}

// ---------------- RoPE (in place), exact IEEE mul/add (VALIDATED) ----------------
__global__ void __launch_bounds__(256) rope_kernel(
    float* __restrict__ x, const float* __restrict__ cs,
    const float* __restrict__ sn, int nheads)
{
    int idx = blockIdx.x * 256 + threadIdx.x;
    int d = idx & 63;
    int h = (idx >> 6) % nheads;
    int token = idx / (nheads * 64);
    float* row = x + ((size_t)token * nheads + h) * HD;
    const float* cr = cs + (size_t)token * HD;
    const float* sr = sn + (size_t)token * HD;
    float a = row[d], b = row[d + 64];
    row[d]      = __fadd_rn(__fmul_rn(a, cr[d]),      __fmul_rn(-b, sr[d]));
    row[d + 64] = __fadd_rn(__fmul_rn(b, cr[d + 64]), __fmul_rn(a, sr[d + 64]));
}

// ---------------- single-pass flash attention (online softmax, deferred normalization) ----------------
// exp computed ONCE per score; no spill. O = (sum e*v) * (1/Z) at the end — the
// deferred-normalization rounding difference (~3e-7 rel) is far under the flip-amplifier budget.
#define FLASH_SMEM ((2 * 64 * 132 + 64 * 68) * 4)
__global__ void __launch_bounds__(256, 2) flash1p_kernel(
    const float* __restrict__ Q, const float* __restrict__ K,
    const float* __restrict__ V, float* __restrict__ O)
{
    extern __shared__ float sm[];
    float* Qs = sm;                // [64][132]
    float* Bf = sm + 64 * 132;     // K tile or V tile [64][132]
    float* Ps = sm + 2 * 64 * 132; // [64][68]

    const int qt = blockIdx.x;
    const int bh = blockIdx.y;
    const int b = bh >> 5;
    const int h = bh & 31;
    const int kvh = h >> 2;
    const int q0 = qt * 64;
    const int t = threadIdx.x;
    const int tx = t & 15;
    const int ty = t >> 4;
    const float scale = 0.08838834764831845f;   // 128^-0.5
    const float FMIN = -3.40282347e38f;         // finfo(f32).min

    const float* Qb = Q + ((size_t)(b * SEQ + q0) * NHEADS + h) * HD;
    #pragma unroll
    for (int l = 0; l < 8; l++) {
        int f = t + l * 256;
        int r = f >> 5;
        int dq = f & 31;
        *(float4*)&Qs[r * 132 + dq * 4] = *(const float4*)&Qb[(size_t)r * 4096 + dq * 4];
    }

    float m_i[4], l_i[4], o[4][8];
    #pragma unroll
    for (int i = 0; i < 4; i++) {
        m_i[i] = -INFINITY; l_i[i] = 0.f;
        #pragma unroll
        for (int dd = 0; dd < 8; dd++) o[i][dd] = 0.f;
    }

    const int ntiles = qt + 1;
    for (int jt = 0; jt < ntiles; jt++) {
        const int k0 = jt * 64;
        const float* Kb = K + ((size_t)(b * SEQ + k0) * NKV + kvh) * HD;
        __syncthreads();   // prior O-update done with Bf/Ps
        #pragma unroll
        for (int l = 0; l < 8; l++) {
            int f = t + l * 256;
            int r = f >> 5;
            int dq = f & 31;
            *(float4*)&Bf[r * 132 + dq * 4] = *(const float4*)&Kb[(size_t)r * 1024 + dq * 4];
        }
        __syncthreads();

        // S = Q K^T
        float acc[4][4];
        #pragma unroll
        for (int i = 0; i < 4; i++)
            #pragma unroll
            for (int j = 0; j < 4; j++) acc[i][j] = 0.f;
        #pragma unroll 8
        for (int d4 = 0; d4 < 32; d4++) {
            float4 qa[4], kb[4];
            #pragma unroll
            for (int i = 0; i < 4; i++)
                qa[i] = *(const float4*)&Qs[(ty + 16 * i) * 132 + d4 * 4];
            #pragma unroll
            for (int j = 0; j < 4; j++)
                kb[j] = *(const float4*)&Bf[(tx + 16 * j) * 132 + d4 * 4];
            #pragma unroll
            for (int i = 0; i < 4; i++)
                #pragma unroll
                for (int j = 0; j < 4; j++) {
                    acc[i][j] = __fmaf_rn(qa[i].x, kb[j].x, acc[i][j]);
                    acc[i][j] = __fmaf_rn(qa[i].y, kb[j].y, acc[i][j]);
                    acc[i][j] = __fmaf_rn(qa[i].z, kb[j].z, acc[i][j]);
                    acc[i][j] = __fmaf_rn(qa[i].w, kb[j].w, acc[i][j]);
                }
        }

        const bool diag = (jt == qt);
        #pragma unroll
        for (int i = 0; i < 4; i++) {
            int r = ty + 16 * i;
            #pragma unroll
            for (int j = 0; j < 4; j++) {
                int c = tx + 16 * j;
                float s = __fmul_rn(acc[i][j], scale);
                if (diag && c > r) s = FMIN;
                acc[i][j] = s;
            }
        }

        // online softmax (exp once per element; rescale running o by al)
        #pragma unroll
        for (int i = 0; i < 4; i++) {
            float rm = fmaxf(fmaxf(acc[i][0], acc[i][1]), fmaxf(acc[i][2], acc[i][3]));
            #pragma unroll
            for (int sft = 1; sft < 16; sft <<= 1)
                rm = fmaxf(rm, __shfl_xor_sync(0xffffffffu, rm, sft));
            float mn = fmaxf(m_i[i], rm);
            float al = (m_i[i] == -INFINITY) ? 0.f : __nv_expf(__fadd_rn(m_i[i], -mn));
            m_i[i] = mn;
            float rs = 0.f;
            #pragma unroll
            for (int j = 0; j < 4; j++) {
                float p = __nv_expf(__fadd_rn(acc[i][j], -mn));   // 0 for masked (FMIN)
                acc[i][j] = p;
                rs = __fadd_rn(rs, p);
            }
            #pragma unroll
            for (int sft = 1; sft < 16; sft <<= 1)
                rs = __fadd_rn(rs, __shfl_xor_sync(0xffffffffu, rs, sft));
            l_i[i] = __fadd_rn(__fmul_rn(l_i[i], al), rs);
            #pragma unroll
            for (int dd = 0; dd < 8; dd++) o[i][dd] = __fmul_rn(o[i][dd], al);
            #pragma unroll
            for (int j = 0; j < 4; j++)
                Ps[(ty + 16 * i) * 68 + tx + 16 * j] = acc[i][j];
        }
        __syncthreads();   // S-phase done with Bf, Ps complete

        const float* Vb = V + ((size_t)(b * SEQ + k0) * NKV + kvh) * HD;
        #pragma unroll
        for (int l = 0; l < 8; l++) {
            int f = t + l * 256;
            int r = f >> 5;
            int dq = f & 31;
            *(float4*)&Bf[r * 132 + dq * 4] = *(const float4*)&Vb[(size_t)r * 1024 + dq * 4];
        }
        __syncthreads();

        // O += P V
        #pragma unroll 4
        for (int j = 0; j < 64; j++) {
            float pj[4];
            #pragma unroll
            for (int i = 0; i < 4; i++) pj[i] = Ps[(ty + 16 * i) * 68 + j];
            float4 v0 = *(const float4*)&Bf[j * 132 + tx * 8];
            float4 v1 = *(const float4*)&Bf[j * 132 + tx * 8 + 4];
            #pragma unroll
            for (int i = 0; i < 4; i++) {
                o[i][0] = __fmaf_rn(pj[i], v0.x, o[i][0]);
                o[i][1] = __fmaf_rn(pj[i], v0.y, o[i][1]);
                o[i][2] = __fmaf_rn(pj[i], v0.z, o[i][2]);
                o[i][3] = __fmaf_rn(pj[i], v0.w, o[i][3]);
                o[i][4] = __fmaf_rn(pj[i], v1.x, o[i][4]);
                o[i][5] = __fmaf_rn(pj[i], v1.y, o[i][5]);
                o[i][6] = __fmaf_rn(pj[i], v1.z, o[i][6]);
                o[i][7] = __fmaf_rn(pj[i], v1.w, o[i][7]);
            }
        }
    }

    #pragma unroll
    for (int i = 0; i < 4; i++) {
        int r = ty + 16 * i;
        float inv = __fdiv_rn(1.0f, l_i[i]);
        float* dst = O + ((size_t)(b * SEQ + q0 + r) * HIDDEN) + h * HD + tx * 8;
        #pragma unroll
        for (int dd = 0; dd < 8; dd++)
            dst[dd] = __fmul_rn(o[i][dd], inv);
    }
}

// ---------------- launch ----------------
extern "C" void kernel_launch(void* const* d_in, const int* in_sizes, int n_in,
                              void* d_out, int out_size)
{
    const float* hidden = (const float*)d_in[0];
    const float* cosp   = (const float*)d_in[1];
    const float* sinp   = (const float*)d_in[2];
    const float* Wq     = (const float*)d_in[3];
    const float* Wk     = (const float*)d_in[4];
    const float* Wv     = (const float*)d_in[5];
    const float* Wo     = (const float*)d_in[6];
    const int* idx_q    = (const int*)d_in[7];
    const int* idx_k    = (const int*)d_in[8];
    const int* idx_v    = (const int*)d_in[9];
    const int* idx_o    = (const int*)d_in[10];
    float* out = (float*)d_out;

    int8_t *X8, *W8;
    float *Xs, *Ws, *Qp, *Kp, *Vp, *AO;
    cudaGetSymbolAddress((void**)&X8, g_X8);
    cudaGetSymbolAddress((void**)&W8, g_W8);
    cudaGetSymbolAddress((void**)&Xs, g_Xs);
    cudaGetSymbolAddress((void**)&Ws, g_Ws);
    cudaGetSymbolAddress((void**)&Qp, g_Qp);
    cudaGetSymbolAddress((void**)&Kp, g_Kp);
    cudaGetSymbolAddress((void**)&Vp, g_Vp);
    cudaGetSymbolAddress((void**)&AO, g_AO);

    cudaFuncSetAttribute(flash1p_kernel, cudaFuncAttributeMaxDynamicSharedMemorySize, FLASH_SMEM);

    dim3 gQO(32, 32), gKV(8, 32);

    // Q projection (EXACT int8 tensor cores, pipelined)
    quant8_rows_kernel<<<4096, 256>>>(hidden, idx_q, X8, Xs);
    quant8_rows_kernel<<<4096, 256>>>(Wq, idx_q, W8, Ws);
    proj_imma_kernel<<<gQO, 256>>>(X8, Xs, W8, Ws, Qp, 4096);
    // K projection
    quant8_rows_kernel<<<4096, 256>>>(hidden, idx_k, X8, Xs);
    quant8_rows_kernel<<<1024, 256>>>(Wk, idx_k, W8, Ws);
    proj_imma_kernel<<<gKV, 256>>>(X8, Xs, W8, Ws, Kp, 1024);
    // V projection
    quant8_rows_kernel<<<4096, 256>>>(hidden, idx_v, X8, Xs);
    quant8_rows_kernel<<<1024, 256>>>(Wv, idx_v, W8, Ws);
    proj_imma_kernel<<<gKV, 256>>>(X8, Xs, W8, Ws, Vp, 1024);
    // RoPE (exact elementwise)
    rope_kernel<<<(4096 * 32 * 64) / 256, 256>>>(Qp, cosp, sinp, 32);
    rope_kernel<<<(4096 * 8 * 64) / 256, 256>>>(Kp, cosp, sinp, 8);
    // attention (single-pass online softmax, deferred normalization)
    flash1p_kernel<<<dim3(32, 64), 256, FLASH_SMEM>>>(Qp, Kp, Vp, AO);
    // O projection -> final output
    quant8_rows_kernel<<<4096, 256>>>(AO, idx_o, X8, Xs);
    quant8_rows_kernel<<<4096, 256>>>(Wo, idx_o, W8, Ws);
    proj_imma_kernel<<<gQO, 256>>>(X8, Xs, W8, Ws, out, 4096);
}